// round 15
// baseline (speedup 1.0000x reference)
#include <cuda_runtime.h>
#include <cuda_fp16.h>
#include <math.h>
#include <stdint.h>

#define BATCH 4
#define CH    512
#define HWN   4096
#define NGROUPS 32
#define CPG   16

#define TM 128
#define TN 128
#define TK 64
#define STAGES 3

// ---------------- scratch (device globals; allocation-free) ----------------
__device__ __half g_h[(size_t)BATCH * CH * HWN];
__device__ __half g_qkv[3 * (size_t)BATCH * CH * HWN];   // q,k,v contiguous
__device__ __half g_o[(size_t)BATCH * CH * HWN];
__device__ __half g_s[(size_t)BATCH * HWN * HWN];   // unnormalized exp(S)
__device__ float  g_l[(size_t)BATCH * HWN];         // row sums
__device__ __half g_w[4 * CH * CH];                 // fp16 weights q,k,v,o
__device__ float  g_bias[3 * CH];                   // staged biases q,k,v
__device__ float  g_stats[BATCH * NGROUPS][8][2];   // GN partial sum/sumsq (no atomics)

// ---------------- helpers ----------------
__device__ __forceinline__ uint32_t smem_u32(const void* p) {
    return (uint32_t)__cvta_generic_to_shared(p);
}
__device__ __forceinline__ void cp16(uint32_t dst, const void* src) {
    asm volatile("cp.async.cg.shared.global [%0], [%1], 16;\n" :: "r"(dst), "l"(src));
}
__device__ __forceinline__ void cp_commit() {
    asm volatile("cp.async.commit_group;\n");
}
template<int N> __device__ __forceinline__ void cp_wait() {
    asm volatile("cp.async.wait_group %0;\n" :: "n"(N));
}
__device__ __forceinline__ void ldmx4(uint32_t* r, uint32_t a) {
    asm volatile("ldmatrix.sync.aligned.m8n8.x4.shared.b16 {%0,%1,%2,%3}, [%4];"
        : "=r"(r[0]), "=r"(r[1]), "=r"(r[2]), "=r"(r[3]) : "r"(a));
}
__device__ __forceinline__ void ldmx4t(uint32_t* r, uint32_t a) {
    asm volatile("ldmatrix.sync.aligned.m8n8.x4.trans.shared.b16 {%0,%1,%2,%3}, [%4];"
        : "=r"(r[0]), "=r"(r[1]), "=r"(r[2]), "=r"(r[3]) : "r"(a));
}
__device__ __forceinline__ void mma_f16(float* d, const uint32_t* a, const uint32_t* b) {
    asm volatile(
        "mma.sync.aligned.m16n8k16.row.col.f32.f16.f16.f32 "
        "{%0,%1,%2,%3}, {%4,%5,%6,%7}, {%8,%9}, {%0,%1,%2,%3};"
        : "+f"(d[0]), "+f"(d[1]), "+f"(d[2]), "+f"(d[3])
        : "r"(a[0]), "r"(a[1]), "r"(a[2]), "r"(a[3]), "r"(b[0]), "r"(b[1]));
}
__device__ __forceinline__ void mma_f16h(uint32_t* d, const uint32_t* a, const uint32_t* b) {
    asm volatile(
        "mma.sync.aligned.m16n8k16.row.col.f16.f16.f16.f16 "
        "{%0,%1}, {%2,%3,%4,%5}, {%6,%7}, {%0,%1};"
        : "+r"(d[0]), "+r"(d[1])
        : "r"(a[0]), "r"(a[1]), "r"(a[2]), "r"(a[3]), "r"(b[0]), "r"(b[1]));
}

// ---------------- fused prologue: GN partial stats + weight/bias staging ----
// blocks [0, 1024): GN partial stats, 8 parts per (batch,group), slot-written
// blocks [1024, 1088): weight fp32->fp16 (1M elems), bias staging, zero g_l
__global__ void prologue_kernel(const float* __restrict__ x,
                                const float* __restrict__ w0, const float* __restrict__ w1,
                                const float* __restrict__ w2, const float* __restrict__ w3,
                                const float* __restrict__ b0, const float* __restrict__ b1,
                                const float* __restrict__ b2,
                                float (*__restrict__ stats)[8][2],
                                __half* __restrict__ wdst, float* __restrict__ bdst,
                                float* __restrict__ L) {
    const int tid = threadIdx.x;
    if (blockIdx.x < 1024) {
        const int bg   = blockIdx.x >> 3;
        const int part = blockIdx.x & 7;
        const float4* xp = reinterpret_cast<const float4*>(x) + (size_t)bg * 16384 + part * 2048;

        float s = 0.f, ss = 0.f;
        #pragma unroll
        for (int i = 0; i < 8; i++) {
            float4 v = xp[tid + i * 256];
            s  += v.x + v.y + v.z + v.w;
            ss += v.x * v.x + v.y * v.y + v.z * v.z + v.w * v.w;
        }
        __shared__ float sh1[256], sh2[256];
        sh1[tid] = s; sh2[tid] = ss;
        __syncthreads();
        for (int o = 128; o > 0; o >>= 1) {
            if (tid < o) { sh1[tid] += sh1[tid + o]; sh2[tid] += sh2[tid + o]; }
            __syncthreads();
        }
        if (tid == 0) {
            stats[bg][part][0] = sh1[0];
            stats[bg][part][1] = sh2[0];
        }
    } else {
        const int wb = blockIdx.x - 1024;            // 0..63
        const int gt = wb * 256 + tid;               // 0..16383
        // zero row sums (16384 floats)
        L[gt] = 0.f;
        // weights: 4*512*512 = 1,048,576 elems; 64 elems per thread
        const int n = CH * CH;
        const float* srcs[4] = {w0, w1, w2, w3};
        #pragma unroll
        for (int i = 0; i < 64; i++) {
            int idx = gt + i * 16384;
            wdst[idx] = __float2half(srcs[idx / n][idx % n]);
        }
        // biases
        if (wb == 0) {
            const float* bs[3] = {b0, b1, b2};
            for (int idx = tid; idx < 3 * CH; idx += 256)
                bdst[idx] = bs[idx / CH][idx % CH];
        }
    }
}

// ---------------- GroupNorm apply (sums partial stats; fp32 in, fp16 out) --
__global__ void gn_apply_kernel(const float* __restrict__ x,
                                const float* __restrict__ gamma,
                                const float* __restrict__ beta,
                                const float (*__restrict__ stats)[8][2],
                                __half* __restrict__ h) {
    const size_t f = (size_t)blockIdx.x * blockDim.x + threadIdx.x;  // float4 index
    const int per_b = CH * HWN / 4;
    const int b = (int)(f / per_b);
    const int r = (int)(f % per_b);
    const int c = r / (HWN / 4);
    const int bg = b * NGROUPS + c / CPG;

    float sum = 0.f, sumsq = 0.f;
    #pragma unroll
    for (int p = 0; p < 8; p++) { sum += stats[bg][p][0]; sumsq += stats[bg][p][1]; }
    const float mean = sum * (1.f / 65536.f);
    const float var  = sumsq * (1.f / 65536.f) - mean * mean;
    const float inv  = rsqrtf(var + 1e-6f);
    const float sc = gamma[c] * inv;
    const float of = beta[c] - mean * sc;

    float4 v = reinterpret_cast<const float4*>(x)[f];
    __half2 h01 = __floats2half2_rn(v.x * sc + of, v.y * sc + of);
    __half2 h23 = __floats2half2_rn(v.z * sc + of, v.w * sc + of);
    uint2 pk;
    pk.x = *reinterpret_cast<uint32_t*>(&h01);
    pk.y = *reinterpret_cast<uint32_t*>(&h23);
    reinterpret_cast<uint2*>(h)[f] = pk;
}

// ---------------- FP16 tensor-core GEMM, 3-stage cp.async, TK=64 -----------
// C[m,n] = op(A)*op(B); ATRANS: A stored [K,M]; BTRANS: B stored [N,K]
// EPI: 2 +bias+res (float out, f32 acc), 6 merged QKV +bias (half out, f32 acc),
//      4 exp+rowsum (half out, f16 acc), 5 col-normalize (half out, f16 acc)
template<bool ATRANS, bool BTRANS, int EPI>
__global__ __launch_bounds__(256, 2)
void gemm_f16(const __half* __restrict__ Ag, const __half* __restrict__ Bg,
              void* __restrict__ Cg,
              const float* __restrict__ bias, const float* __restrict__ res,
              float* __restrict__ Lsum,
              int K, int lda, int ldb, int ldc,
              size_t strA, size_t strB, size_t strC, float scale)
{
    extern __shared__ __half smem[];
    constexpr int SA = ATRANS ? (TM + 8) : (TK + 8);
    constexpr int SB = BTRANS ? (TK + 8) : (TN + 8);
    constexpr int SZA = ATRANS ? TK * SA : TM * SA;
    constexpr int SZB = BTRANS ? TN * SB : TK * SB;
    constexpr int STG = SZA + SZB;
    constexpr bool HAS_BIAS = (EPI == 2 || EPI == 6);
    constexpr bool F16ACC = (EPI == 4 || EPI == 5);
    constexpr int ACH = ATRANS ? TM / 8 : TK / 8;
    constexpr int ANR = ATRANS ? TK : TM;
    constexpr int BCH = BTRANS ? TK / 8 : TN / 8;
    constexpr int BNR = BTRANS ? TN : TK;

    const int zz = blockIdx.z;
    const int proj = (EPI == 6) ? (zz >> 2) : 0;
    const int bz   = (EPI == 6) ? (zz & 3)  : zz;
    const int m0 = blockIdx.y * TM;
    const int n0 = blockIdx.x * TN;
    const __half* A = Ag + ((EPI == 6) ? (size_t)proj * CH * CH : (size_t)bz * strA);
    const __half* B = Bg + (size_t)bz * strB;
    const size_t coff = (EPI == 6) ? ((size_t)proj * BATCH + bz) * strC
                                   : (size_t)bz * strC;
    const float* R = (EPI == 2) ? (res + coff) : nullptr;
    const float* Bi = HAS_BIAS ? (bias + ((EPI == 6) ? proj * CH : 0)) : nullptr;
    float* L = (EPI == 4 || EPI == 5) ? (Lsum + (size_t)bz * HWN) : nullptr;

    const int tid  = threadIdx.x;
    const int wid  = tid >> 5;
    const int lane = tid & 31;
    const int gid  = lane >> 2;
    const int tig  = lane & 3;
    const int wm   = (wid >> 2) * 64;
    const int wn   = (wid & 3) * 32;
    const int lq   = lane >> 3;
    const int lr   = lane & 7;

    auto copy_tile = [&](int kt, int st) {
        __half* as = smem + st * STG;
        __half* bs = as + SZA;
        const int k0 = kt * TK;
        #pragma unroll
        for (int i = 0; i < ANR * ACH / 256; i++) {
            int idx = tid + i * 256;
            int r = idx / ACH, c = idx % ACH;
            if (ATRANS)
                cp16(smem_u32(as + r * SA + c * 8), A + (size_t)(k0 + r) * lda + m0 + c * 8);
            else
                cp16(smem_u32(as + r * SA + c * 8), A + (size_t)(m0 + r) * lda + k0 + c * 8);
        }
        #pragma unroll
        for (int i = 0; i < BNR * BCH / 256; i++) {
            int idx = tid + i * 256;
            int r = idx / BCH, c = idx % BCH;
            if (BTRANS)
                cp16(smem_u32(bs + r * SB + c * 8), B + (size_t)(n0 + r) * ldb + k0 + c * 8);
            else
                cp16(smem_u32(bs + r * SB + c * 8), B + (size_t)(k0 + r) * ldb + n0 + c * 8);
        }
    };

    float    accf[4][4][4] = {};
    uint32_t acch[4][4][2] = {};
    const int KT = K / TK;

    copy_tile(0, 0); cp_commit();
    copy_tile(1, 1); cp_commit();

    for (int kt = 0; kt < KT; kt++) {
        cp_wait<1>();
        __syncthreads();
        if (kt + 2 < KT) copy_tile(kt + 2, (kt + 2) % STAGES);
        cp_commit();

        const __half* as = smem + (kt % STAGES) * STG;
        const __half* bs = as + SZA;

        #pragma unroll
        for (int ks = 0; ks < TK / 16; ks++) {
            const int kk = ks * 16;
            uint32_t a[4][4], b[2][4];
            #pragma unroll
            for (int i = 0; i < 4; i++) {
                const int mb = wm + i * 16;
                if (ATRANS)
                    ldmx4t(a[i], smem_u32(as + (size_t)(kk + (lq >> 1) * 8 + lr) * SA
                                             + mb + (lq & 1) * 8));
                else
                    ldmx4(a[i], smem_u32(as + (size_t)(mb + lr + (lq & 1) * 8) * SA
                                            + kk + (lq >> 1) * 8));
            }
            #pragma unroll
            for (int jj = 0; jj < 2; jj++) {
                const int nb = wn + jj * 16;
                if (BTRANS)
                    ldmx4(b[jj], smem_u32(bs + (size_t)(nb + (lq >> 1) * 8 + lr) * SB
                                             + kk + (lq & 1) * 8));
                else
                    ldmx4t(b[jj], smem_u32(bs + (size_t)(kk + (lq & 1) * 8 + lr) * SB
                                              + nb + (lq >> 1) * 8));
            }
            #pragma unroll
            for (int i = 0; i < 4; i++)
                #pragma unroll
                for (int j = 0; j < 4; j++) {
                    if (F16ACC) mma_f16h(acch[i][j], a[i], &b[j >> 1][(j & 1) * 2]);
                    else        mma_f16 (accf[i][j], a[i], &b[j >> 1][(j & 1) * 2]);
                }
        }
    }

    __syncthreads();

    // ---- epilogue ----
    #pragma unroll
    for (int i = 0; i < 4; i++) {
        const int r0 = m0 + wm + i * 16 + gid;
        float b0v = 0.f, b1v = 0.f;
        if (HAS_BIAS) { b0v = Bi[r0]; b1v = Bi[r0 + 8]; }
        float rsum0 = 0.f, rsum1 = 0.f;
        #pragma unroll
        for (int j = 0; j < 4; j++) {
            const int c0 = n0 + wn + j * 8 + tig * 2;
            size_t i0 = (size_t)r0 * ldc + c0;
            size_t i1 = (size_t)(r0 + 8) * ldc + c0;
            float2 v0, v1;
            if (F16ACC) {
                __half2 p0 = *reinterpret_cast<__half2*>(&acch[i][j][0]);
                __half2 p1 = *reinterpret_cast<__half2*>(&acch[i][j][1]);
                v0 = __half22float2(p0);
                v1 = __half22float2(p1);
            } else {
                v0 = make_float2(accf[i][j][0], accf[i][j][1]);
                v1 = make_float2(accf[i][j][2], accf[i][j][3]);
            }
            if (HAS_BIAS) { v0.x += b0v; v0.y += b0v; v1.x += b1v; v1.y += b1v; }
            if (EPI == 2) {
                float2 r0v = *reinterpret_cast<const float2*>(&R[i0]);
                float2 r1v = *reinterpret_cast<const float2*>(&R[i1]);
                v0.x += r0v.x; v0.y += r0v.y; v1.x += r1v.x; v1.y += r1v.y;
            }
            if (EPI == 4) {
                v0.x = __expf(v0.x * scale); v0.y = __expf(v0.y * scale);
                v1.x = __expf(v1.x * scale); v1.y = __expf(v1.y * scale);
                rsum0 += v0.x + v0.y;
                rsum1 += v1.x + v1.y;
            }
            if (EPI == 5) {
                float l0 = L[c0], l1 = L[c0 + 1];
                v0.x /= l0; v0.y /= l1;
                v1.x /= l0; v1.y /= l1;
            }
            if (EPI == 2) {
                float* C = (float*)Cg + coff;
                *reinterpret_cast<float2*>(&C[i0]) = v0;
                *reinterpret_cast<float2*>(&C[i1]) = v1;
            } else {
                __half* C = (__half*)Cg + coff;
                *reinterpret_cast<__half2*>(&C[i0]) = __floats2half2_rn(v0.x, v0.y);
                *reinterpret_cast<__half2*>(&C[i1]) = __floats2half2_rn(v1.x, v1.y);
            }
        }
        if (EPI == 4) {
            rsum0 += __shfl_xor_sync(0xffffffffu, rsum0, 1);
            rsum0 += __shfl_xor_sync(0xffffffffu, rsum0, 2);
            rsum1 += __shfl_xor_sync(0xffffffffu, rsum1, 1);
            rsum1 += __shfl_xor_sync(0xffffffffu, rsum1, 2);
            if (tig == 0) {
                atomicAdd(&L[r0], rsum0);
                atomicAdd(&L[r0 + 8], rsum1);
            }
        }
    }
}

// ---------------- launch ----------------
extern "C" void kernel_launch(void* const* d_in, const int* in_sizes, int n_in,
                              void* d_out, int out_size) {
    const float* x        = (const float*)d_in[0];
    const float* gn_gamma = (const float*)d_in[1];
    const float* gn_beta  = (const float*)d_in[2];
    const float* wq       = (const float*)d_in[3];
    const float* bq       = (const float*)d_in[4];
    const float* wk       = (const float*)d_in[5];
    const float* bk       = (const float*)d_in[6];
    const float* wv       = (const float*)d_in[7];
    const float* bv       = (const float*)d_in[8];
    const float* wo       = (const float*)d_in[9];
    const float* bo       = (const float*)d_in[10];
    float* out = (float*)d_out;

    __half *ph, *pqkv, *po, *ps, *pw;
    float *pl, *pb;
    float (*pst)[8][2];
    cudaGetSymbolAddress((void**)&ph, g_h);
    cudaGetSymbolAddress((void**)&pqkv, g_qkv);
    cudaGetSymbolAddress((void**)&po, g_o);
    cudaGetSymbolAddress((void**)&ps, g_s);
    cudaGetSymbolAddress((void**)&pl, g_l);
    cudaGetSymbolAddress((void**)&pw, g_w);
    cudaGetSymbolAddress((void**)&pb, g_bias);
    cudaGetSymbolAddress((void**)&pst, g_stats);

    const size_t sCH = (size_t)CH * HWN;
    const size_t sSS = (size_t)HWN * HWN;
    const float scale = 0.04419417382415922f; // 512^-0.5
    const int WS = CH * CH;
    __half* pq = pqkv;
    __half* pk = pqkv + (size_t)BATCH * sCH;
    __half* pv = pqkv + 2 * (size_t)BATCH * sCH;

    const int smem_ff = STAGES * (TM * (TK + 8) + TK * (TN + 8)) * 2;
    const int smem_tf = STAGES * (TK * (TM + 8) + TK * (TN + 8)) * 2;
    const int smem_ft = STAGES * (TM * (TK + 8) + TN * (TK + 8)) * 2;

    cudaFuncSetAttribute(gemm_f16<false, false, 6>, cudaFuncAttributeMaxDynamicSharedMemorySize, smem_ff);
    cudaFuncSetAttribute(gemm_f16<false, false, 2>, cudaFuncAttributeMaxDynamicSharedMemorySize, smem_ff);
    cudaFuncSetAttribute(gemm_f16<true,  false, 4>, cudaFuncAttributeMaxDynamicSharedMemorySize, smem_tf);
    cudaFuncSetAttribute(gemm_f16<false, true,  5>, cudaFuncAttributeMaxDynamicSharedMemorySize, smem_ft);

    // 0) fused prologue: GN partial stats + weight/bias staging + L zeroing
    prologue_kernel<<<1088, 256>>>(x, wq, wk, wv, wo, bq, bk, bv, pst, pw, pb, pl);

    // 1) GroupNorm apply (sums partials) -> fp16 h
    gn_apply_kernel<<<(int)(BATCH * sCH / 4 / 256), 256>>>(x, gn_gamma, gn_beta, pst, ph);

    // 2) merged q,k,v projections: z = proj*4 + batch
    dim3 pg3(HWN / TN, CH / TM, 3 * BATCH);
    gemm_f16<false, false, 6><<<pg3, 256, smem_ff>>>(pw, ph, pqkv, pb, nullptr, nullptr,
        CH, CH, HWN, HWN, 0, sCH, sCH, 1.f);

    // 3) P~[n,m] = exp(scale * Q^T K) (fp16), row sums -> g_l  [f16 acc]
    dim3 sg(HWN / TN, HWN / TM, BATCH);
    gemm_f16<true, false, 4><<<sg, 256, smem_tf>>>(pq, pk, ps, nullptr, nullptr, pl,
        CH, HWN, HWN, HWN, sCH, sCH, sSS, scale);

    // 4) O[c,n] = (sum_m V[c,m] P~[n,m]) / l[n] (fp16)  [f16 acc]
    dim3 ag(HWN / TN, CH / TM, BATCH);
    gemm_f16<false, true, 5><<<ag, 256, smem_ft>>>(pv, ps, po, nullptr, nullptr, pl,
        HWN, HWN, HWN, HWN, sCH, sSS, sCH, 1.f);

    // 5) out projection + bias + residual (fp32 out)
    dim3 pg(HWN / TN, CH / TM, BATCH);
    gemm_f16<false, false, 2><<<pg, 256, smem_ff>>>(pw + 3 * WS, po, out, bo, x, nullptr,
        CH, CH, HWN, HWN, 0, sCH, sCH, 1.f);
}

// round 16
// speedup vs baseline: 1.0251x; 1.0251x over previous
#include <cuda_runtime.h>
#include <cuda_fp16.h>
#include <math.h>
#include <stdint.h>

#define BATCH 4
#define CH    512
#define HWN   4096
#define NGROUPS 32
#define CPG   16

#define TM 128
#define TN 128
#define TK 64
#define STAGES 3

// ---------------- scratch (device globals; allocation-free) ----------------
__device__ __half g_h[(size_t)BATCH * CH * HWN];
__device__ __half g_qkv[3 * (size_t)BATCH * CH * HWN];   // q,k,v contiguous
__device__ __half g_o[(size_t)BATCH * CH * HWN];
__device__ __half g_s[(size_t)BATCH * HWN * HWN];   // unnormalized exp(S)
__device__ float  g_l[(size_t)BATCH * HWN];         // row sums
__device__ __half g_w[4 * CH * CH];                 // fp16 weights q,k,v,o
__device__ float  g_bias[3 * CH];                   // staged biases q,k,v
__device__ float  g_stats[BATCH * NGROUPS][8][2];   // GN partial sum/sumsq (slots)

// ---------------- helpers ----------------
__device__ __forceinline__ uint32_t smem_u32(const void* p) {
    return (uint32_t)__cvta_generic_to_shared(p);
}
__device__ __forceinline__ void cp16(uint32_t dst, const void* src) {
    asm volatile("cp.async.cg.shared.global [%0], [%1], 16;\n" :: "r"(dst), "l"(src));
}
__device__ __forceinline__ void cp_commit() {
    asm volatile("cp.async.commit_group;\n");
}
template<int N> __device__ __forceinline__ void cp_wait() {
    asm volatile("cp.async.wait_group %0;\n" :: "n"(N));
}
__device__ __forceinline__ void ldmx4(uint32_t* r, uint32_t a) {
    asm volatile("ldmatrix.sync.aligned.m8n8.x4.shared.b16 {%0,%1,%2,%3}, [%4];"
        : "=r"(r[0]), "=r"(r[1]), "=r"(r[2]), "=r"(r[3]) : "r"(a));
}
__device__ __forceinline__ void ldmx4t(uint32_t* r, uint32_t a) {
    asm volatile("ldmatrix.sync.aligned.m8n8.x4.trans.shared.b16 {%0,%1,%2,%3}, [%4];"
        : "=r"(r[0]), "=r"(r[1]), "=r"(r[2]), "=r"(r[3]) : "r"(a));
}
__device__ __forceinline__ void mma_f16(float* d, const uint32_t* a, const uint32_t* b) {
    asm volatile(
        "mma.sync.aligned.m16n8k16.row.col.f32.f16.f16.f32 "
        "{%0,%1,%2,%3}, {%4,%5,%6,%7}, {%8,%9}, {%0,%1,%2,%3};"
        : "+f"(d[0]), "+f"(d[1]), "+f"(d[2]), "+f"(d[3])
        : "r"(a[0]), "r"(a[1]), "r"(a[2]), "r"(a[3]), "r"(b[0]), "r"(b[1]));
}
__device__ __forceinline__ void mma_f16h(uint32_t* d, const uint32_t* a, const uint32_t* b) {
    asm volatile(
        "mma.sync.aligned.m16n8k16.row.col.f16.f16.f16.f16 "
        "{%0,%1}, {%2,%3,%4,%5}, {%6,%7}, {%0,%1};"
        : "+r"(d[0]), "+r"(d[1])
        : "r"(a[0]), "r"(a[1]), "r"(a[2]), "r"(a[3]), "r"(b[0]), "r"(b[1]));
}

// ---------------- weight/bias staging ----------------
__global__ void cvt_w_kernel(const float* __restrict__ w0, const float* __restrict__ w1,
                             const float* __restrict__ w2, const float* __restrict__ w3,
                             const float* __restrict__ b0, const float* __restrict__ b1,
                             const float* __restrict__ b2,
                             __half* __restrict__ dst, float* __restrict__ bdst) {
    const int n = CH * CH;
    const float* srcs[4] = {w0, w1, w2, w3};
    for (int idx = blockIdx.x * blockDim.x + threadIdx.x; idx < 4 * n;
         idx += gridDim.x * blockDim.x)
        dst[idx] = __float2half(srcs[idx / n][idx % n]);
    if (blockIdx.x == 0) {
        const float* bs[3] = {b0, b1, b2};
        for (int idx = threadIdx.x; idx < 3 * CH; idx += blockDim.x)
            bdst[idx] = bs[idx / CH][idx % CH];
    }
}

// ---------------- GroupNorm pass 1: partial stats -> slots (no atomics) ----
__global__ void gn_stats_kernel(const float* __restrict__ x,
                                float (*__restrict__ stats)[8][2]) {
    const int bg   = blockIdx.x >> 3;
    const int part = blockIdx.x & 7;
    const float4* xp = reinterpret_cast<const float4*>(x) + (size_t)bg * 16384 + part * 2048;
    const int tid = threadIdx.x;

    float s = 0.f, ss = 0.f;
    #pragma unroll
    for (int i = 0; i < 8; i++) {
        float4 v = xp[tid + i * 256];
        s  += v.x + v.y + v.z + v.w;
        ss += v.x * v.x + v.y * v.y + v.z * v.z + v.w * v.w;
    }
    __shared__ float sh1[256], sh2[256];
    sh1[tid] = s; sh2[tid] = ss;
    __syncthreads();
    for (int o = 128; o > 0; o >>= 1) {
        if (tid < o) { sh1[tid] += sh1[tid + o]; sh2[tid] += sh2[tid + o]; }
        __syncthreads();
    }
    if (tid == 0) {
        stats[bg][part][0] = sh1[0];
        stats[bg][part][1] = sh2[0];
    }
}

// ---------------- GroupNorm pass 2: normalize (fp32 in, fp16 out) ----------
__global__ void gn_apply_kernel(const float* __restrict__ x,
                                const float* __restrict__ gamma,
                                const float* __restrict__ beta,
                                const float (*__restrict__ stats)[8][2],
                                __half* __restrict__ h) {
    const size_t f = (size_t)blockIdx.x * blockDim.x + threadIdx.x;  // float4 index
    const int per_b = CH * HWN / 4;
    const int b = (int)(f / per_b);
    const int r = (int)(f % per_b);
    const int c = r / (HWN / 4);
    const int bg = b * NGROUPS + c / CPG;

    float sum = 0.f, sumsq = 0.f;
    #pragma unroll
    for (int p = 0; p < 8; p++) { sum += stats[bg][p][0]; sumsq += stats[bg][p][1]; }
    const float mean = sum * (1.f / 65536.f);
    const float var  = sumsq * (1.f / 65536.f) - mean * mean;
    const float inv  = rsqrtf(var + 1e-6f);
    const float sc = gamma[c] * inv;
    const float of = beta[c] - mean * sc;

    float4 v = reinterpret_cast<const float4*>(x)[f];
    __half2 h01 = __floats2half2_rn(v.x * sc + of, v.y * sc + of);
    __half2 h23 = __floats2half2_rn(v.z * sc + of, v.w * sc + of);
    uint2 pk;
    pk.x = *reinterpret_cast<uint32_t*>(&h01);
    pk.y = *reinterpret_cast<uint32_t*>(&h23);
    reinterpret_cast<uint2*>(h)[f] = pk;
}

// ---------------- FP16 tensor-core GEMM, 3-stage cp.async, TK=64 -----------
// C[m,n] = op(A)*op(B); ATRANS: A stored [K,M]; BTRANS: B stored [N,K]
// EPI: 2 +bias+res (float out, f32 acc), 6 merged QKV +bias (half out, f32 acc),
//      4 exp+rowsum (half out, f16 acc), 5 col-normalize (half out, f16 acc)
template<bool ATRANS, bool BTRANS, int EPI>
__global__ __launch_bounds__(256, 2)
void gemm_f16(const __half* __restrict__ Ag, const __half* __restrict__ Bg,
              void* __restrict__ Cg,
              const float* __restrict__ bias, const float* __restrict__ res,
              float* __restrict__ Lsum,
              int K, int lda, int ldb, int ldc,
              size_t strA, size_t strB, size_t strC, float scale)
{
    extern __shared__ __half smem[];
    constexpr int SA = ATRANS ? (TM + 8) : (TK + 8);
    constexpr int SB = BTRANS ? (TK + 8) : (TN + 8);
    constexpr int SZA = ATRANS ? TK * SA : TM * SA;
    constexpr int SZB = BTRANS ? TN * SB : TK * SB;
    constexpr int STG = SZA + SZB;
    constexpr bool HAS_BIAS = (EPI == 2 || EPI == 6);
    constexpr bool F16ACC = (EPI == 4 || EPI == 5);
    constexpr int ACH = ATRANS ? TM / 8 : TK / 8;
    constexpr int ANR = ATRANS ? TK : TM;
    constexpr int BCH = BTRANS ? TK / 8 : TN / 8;
    constexpr int BNR = BTRANS ? TN : TK;

    const int zz = blockIdx.z;
    const int proj = (EPI == 6) ? (zz >> 2) : 0;
    const int bz   = (EPI == 6) ? (zz & 3)  : zz;
    const int m0 = blockIdx.y * TM;
    const int n0 = blockIdx.x * TN;
    const __half* A = Ag + ((EPI == 6) ? (size_t)proj * CH * CH : (size_t)bz * strA);
    const __half* B = Bg + (size_t)bz * strB;
    const size_t coff = (EPI == 6) ? ((size_t)proj * BATCH + bz) * strC
                                   : (size_t)bz * strC;
    const float* R = (EPI == 2) ? (res + coff) : nullptr;
    const float* Bi = HAS_BIAS ? (bias + ((EPI == 6) ? proj * CH : 0)) : nullptr;
    float* L = (EPI == 4 || EPI == 5) ? (Lsum + (size_t)bz * HWN) : nullptr;

    const int tid  = threadIdx.x;
    const int wid  = tid >> 5;
    const int lane = tid & 31;
    const int gid  = lane >> 2;
    const int tig  = lane & 3;
    const int wm   = (wid >> 2) * 64;
    const int wn   = (wid & 3) * 32;
    const int lq   = lane >> 3;
    const int lr   = lane & 7;

    auto copy_tile = [&](int kt, int st) {
        __half* as = smem + st * STG;
        __half* bs = as + SZA;
        const int k0 = kt * TK;
        #pragma unroll
        for (int i = 0; i < ANR * ACH / 256; i++) {
            int idx = tid + i * 256;
            int r = idx / ACH, c = idx % ACH;
            if (ATRANS)
                cp16(smem_u32(as + r * SA + c * 8), A + (size_t)(k0 + r) * lda + m0 + c * 8);
            else
                cp16(smem_u32(as + r * SA + c * 8), A + (size_t)(m0 + r) * lda + k0 + c * 8);
        }
        #pragma unroll
        for (int i = 0; i < BNR * BCH / 256; i++) {
            int idx = tid + i * 256;
            int r = idx / BCH, c = idx % BCH;
            if (BTRANS)
                cp16(smem_u32(bs + r * SB + c * 8), B + (size_t)(n0 + r) * ldb + k0 + c * 8);
            else
                cp16(smem_u32(bs + r * SB + c * 8), B + (size_t)(k0 + r) * ldb + n0 + c * 8);
        }
    };

    float    accf[4][4][4] = {};
    uint32_t acch[4][4][2] = {};
    const int KT = K / TK;

    copy_tile(0, 0); cp_commit();
    copy_tile(1, 1); cp_commit();

    for (int kt = 0; kt < KT; kt++) {
        cp_wait<1>();
        __syncthreads();
        if (kt + 2 < KT) copy_tile(kt + 2, (kt + 2) % STAGES);
        cp_commit();

        const __half* as = smem + (kt % STAGES) * STG;
        const __half* bs = as + SZA;

        #pragma unroll
        for (int ks = 0; ks < TK / 16; ks++) {
            const int kk = ks * 16;
            uint32_t a[4][4], b[2][4];
            #pragma unroll
            for (int i = 0; i < 4; i++) {
                const int mb = wm + i * 16;
                if (ATRANS)
                    ldmx4t(a[i], smem_u32(as + (size_t)(kk + (lq >> 1) * 8 + lr) * SA
                                             + mb + (lq & 1) * 8));
                else
                    ldmx4(a[i], smem_u32(as + (size_t)(mb + lr + (lq & 1) * 8) * SA
                                            + kk + (lq >> 1) * 8));
            }
            #pragma unroll
            for (int jj = 0; jj < 2; jj++) {
                const int nb = wn + jj * 16;
                if (BTRANS)
                    ldmx4(b[jj], smem_u32(bs + (size_t)(nb + (lq >> 1) * 8 + lr) * SB
                                             + kk + (lq & 1) * 8));
                else
                    ldmx4t(b[jj], smem_u32(bs + (size_t)(kk + (lq & 1) * 8 + lr) * SB
                                              + nb + (lq >> 1) * 8));
            }
            #pragma unroll
            for (int i = 0; i < 4; i++)
                #pragma unroll
                for (int j = 0; j < 4; j++) {
                    if (F16ACC) mma_f16h(acch[i][j], a[i], &b[j >> 1][(j & 1) * 2]);
                    else        mma_f16 (accf[i][j], a[i], &b[j >> 1][(j & 1) * 2]);
                }
        }
    }

    __syncthreads();

    // ---- epilogue ----
    #pragma unroll
    for (int i = 0; i < 4; i++) {
        const int r0 = m0 + wm + i * 16 + gid;
        float b0v = 0.f, b1v = 0.f;
        if (HAS_BIAS) { b0v = Bi[r0]; b1v = Bi[r0 + 8]; }
        float rsum0 = 0.f, rsum1 = 0.f;
        #pragma unroll
        for (int j = 0; j < 4; j++) {
            const int c0 = n0 + wn + j * 8 + tig * 2;
            size_t i0 = (size_t)r0 * ldc + c0;
            size_t i1 = (size_t)(r0 + 8) * ldc + c0;
            float2 v0, v1;
            if (F16ACC) {
                __half2 p0 = *reinterpret_cast<__half2*>(&acch[i][j][0]);
                __half2 p1 = *reinterpret_cast<__half2*>(&acch[i][j][1]);
                v0 = __half22float2(p0);
                v1 = __half22float2(p1);
            } else {
                v0 = make_float2(accf[i][j][0], accf[i][j][1]);
                v1 = make_float2(accf[i][j][2], accf[i][j][3]);
            }
            if (HAS_BIAS) { v0.x += b0v; v0.y += b0v; v1.x += b1v; v1.y += b1v; }
            if (EPI == 2) {
                float2 r0v = *reinterpret_cast<const float2*>(&R[i0]);
                float2 r1v = *reinterpret_cast<const float2*>(&R[i1]);
                v0.x += r0v.x; v0.y += r0v.y; v1.x += r1v.x; v1.y += r1v.y;
            }
            if (EPI == 4) {
                v0.x = __expf(v0.x * scale); v0.y = __expf(v0.y * scale);
                v1.x = __expf(v1.x * scale); v1.y = __expf(v1.y * scale);
                rsum0 += v0.x + v0.y;
                rsum1 += v1.x + v1.y;
            }
            if (EPI == 5) {
                float l0 = L[c0], l1 = L[c0 + 1];
                v0.x /= l0; v0.y /= l1;
                v1.x /= l0; v1.y /= l1;
            }
            if (EPI == 2) {
                float* C = (float*)Cg + coff;
                *reinterpret_cast<float2*>(&C[i0]) = v0;
                *reinterpret_cast<float2*>(&C[i1]) = v1;
            } else {
                __half* C = (__half*)Cg + coff;
                *reinterpret_cast<__half2*>(&C[i0]) = __floats2half2_rn(v0.x, v0.y);
                *reinterpret_cast<__half2*>(&C[i1]) = __floats2half2_rn(v1.x, v1.y);
            }
        }
        if (EPI == 4) {
            rsum0 += __shfl_xor_sync(0xffffffffu, rsum0, 1);
            rsum0 += __shfl_xor_sync(0xffffffffu, rsum0, 2);
            rsum1 += __shfl_xor_sync(0xffffffffu, rsum1, 1);
            rsum1 += __shfl_xor_sync(0xffffffffu, rsum1, 2);
            if (tig == 0) {
                atomicAdd(&L[r0], rsum0);
                atomicAdd(&L[r0 + 8], rsum1);
            }
        }
    }
}

// ---------------- launch ----------------
extern "C" void kernel_launch(void* const* d_in, const int* in_sizes, int n_in,
                              void* d_out, int out_size) {
    const float* x        = (const float*)d_in[0];
    const float* gn_gamma = (const float*)d_in[1];
    const float* gn_beta  = (const float*)d_in[2];
    const float* wq       = (const float*)d_in[3];
    const float* bq       = (const float*)d_in[4];
    const float* wk       = (const float*)d_in[5];
    const float* bk       = (const float*)d_in[6];
    const float* wv       = (const float*)d_in[7];
    const float* bv       = (const float*)d_in[8];
    const float* wo       = (const float*)d_in[9];
    const float* bo       = (const float*)d_in[10];
    float* out = (float*)d_out;

    __half *ph, *pqkv, *po, *ps, *pw;
    float *pl, *pb;
    float (*pst)[8][2];
    cudaGetSymbolAddress((void**)&ph, g_h);
    cudaGetSymbolAddress((void**)&pqkv, g_qkv);
    cudaGetSymbolAddress((void**)&po, g_o);
    cudaGetSymbolAddress((void**)&ps, g_s);
    cudaGetSymbolAddress((void**)&pl, g_l);
    cudaGetSymbolAddress((void**)&pw, g_w);
    cudaGetSymbolAddress((void**)&pb, g_bias);
    cudaGetSymbolAddress((void**)&pst, g_stats);

    const size_t sCH = (size_t)CH * HWN;
    const size_t sSS = (size_t)HWN * HWN;
    const float scale = 0.04419417382415922f; // 512^-0.5
    const int WS = CH * CH;
    __half* pq = pqkv;
    __half* pk = pqkv + (size_t)BATCH * sCH;
    __half* pv = pqkv + 2 * (size_t)BATCH * sCH;

    const int smem_ff = STAGES * (TM * (TK + 8) + TK * (TN + 8)) * 2;
    const int smem_tf = STAGES * (TK * (TM + 8) + TK * (TN + 8)) * 2;
    const int smem_ft = STAGES * (TM * (TK + 8) + TN * (TK + 8)) * 2;

    cudaFuncSetAttribute(gemm_f16<false, false, 6>, cudaFuncAttributeMaxDynamicSharedMemorySize, smem_ff);
    cudaFuncSetAttribute(gemm_f16<false, false, 2>, cudaFuncAttributeMaxDynamicSharedMemorySize, smem_ff);
    cudaFuncSetAttribute(gemm_f16<true,  false, 4>, cudaFuncAttributeMaxDynamicSharedMemorySize, smem_tf);
    cudaFuncSetAttribute(gemm_f16<false, true,  5>, cudaFuncAttributeMaxDynamicSharedMemorySize, smem_ft);

    // 0) weights/biases -> staged; zero row sums
    cvt_w_kernel<<<256, 256>>>(wq, wk, wv, wo, bq, bk, bv, pw, pb);
    cudaMemsetAsync(pl, 0, (size_t)BATCH * HWN * sizeof(float));

    // 1) GroupNorm: partial stats (slot writes) then apply -> fp16 h
    gn_stats_kernel<<<BATCH * NGROUPS * 8, 256>>>(x, pst);
    gn_apply_kernel<<<(int)(BATCH * sCH / 4 / 256), 256>>>(x, gn_gamma, gn_beta, pst, ph);

    // 2) merged q,k,v projections: z = proj*4 + batch
    dim3 pg3(HWN / TN, CH / TM, 3 * BATCH);
    gemm_f16<false, false, 6><<<pg3, 256, smem_ff>>>(pw, ph, pqkv, pb, nullptr, nullptr,
        CH, CH, HWN, HWN, 0, sCH, sCH, 1.f);

    // 3) P~[n,m] = exp(scale * Q^T K) (fp16), row sums -> g_l  [f16 acc]
    dim3 sg(HWN / TN, HWN / TM, BATCH);
    gemm_f16<true, false, 4><<<sg, 256, smem_tf>>>(pq, pk, ps, nullptr, nullptr, pl,
        CH, HWN, HWN, HWN, sCH, sCH, sSS, scale);

    // 4) O[c,n] = (sum_m V[c,m] P~[n,m]) / l[n] (fp16)  [f16 acc]
    dim3 ag(HWN / TN, CH / TM, BATCH);
    gemm_f16<false, true, 5><<<ag, 256, smem_ft>>>(pv, ps, po, nullptr, nullptr, pl,
        HWN, HWN, HWN, HWN, sCH, sSS, sCH, 1.f);

    // 5) out projection + bias + residual (fp32 out)
    dim3 pg(HWN / TN, CH / TM, BATCH);
    gemm_f16<false, false, 2><<<pg, 256, smem_ff>>>(pw + 3 * WS, po, out, bo, x, nullptr,
        CH, CH, HWN, HWN, 0, sCH, sCH, 1.f);
}

// round 17
// speedup vs baseline: 1.0318x; 1.0065x over previous
#include <cuda_runtime.h>
#include <cuda_fp16.h>
#include <math.h>
#include <stdint.h>

#define BATCH 4
#define CH    512
#define HWN   4096
#define NGROUPS 32
#define CPG   16

#define TM 128
#define TN 128
#define TK 64
#define STAGES 3

// ---------------- scratch (device globals; allocation-free) ----------------
__device__ __half g_h[(size_t)BATCH * CH * HWN];
__device__ __half g_qkv[3 * (size_t)BATCH * CH * HWN];   // q,k,v contiguous
__device__ __half g_o[(size_t)BATCH * CH * HWN];
__device__ __half g_s[(size_t)BATCH * HWN * HWN];   // unnormalized exp(S)
__device__ float  g_l[(size_t)BATCH * HWN];         // row sums
__device__ __half g_w[4 * CH * CH];                 // fp16 weights q,k,v,o
__device__ float  g_bias[3 * CH];                   // staged biases q,k,v
__device__ float  g_stats[BATCH * NGROUPS][8][2];   // GN partial sum/sumsq (slots)

// ---------------- helpers ----------------
__device__ __forceinline__ uint32_t smem_u32(const void* p) {
    return (uint32_t)__cvta_generic_to_shared(p);
}
__device__ __forceinline__ void cp16(uint32_t dst, const void* src) {
    asm volatile("cp.async.cg.shared.global [%0], [%1], 16;\n" :: "r"(dst), "l"(src));
}
__device__ __forceinline__ void cp_commit() {
    asm volatile("cp.async.commit_group;\n");
}
template<int N> __device__ __forceinline__ void cp_wait() {
    asm volatile("cp.async.wait_group %0;\n" :: "n"(N));
}
__device__ __forceinline__ void ldmx4(uint32_t* r, uint32_t a) {
    asm volatile("ldmatrix.sync.aligned.m8n8.x4.shared.b16 {%0,%1,%2,%3}, [%4];"
        : "=r"(r[0]), "=r"(r[1]), "=r"(r[2]), "=r"(r[3]) : "r"(a));
}
__device__ __forceinline__ void ldmx4t(uint32_t* r, uint32_t a) {
    asm volatile("ldmatrix.sync.aligned.m8n8.x4.trans.shared.b16 {%0,%1,%2,%3}, [%4];"
        : "=r"(r[0]), "=r"(r[1]), "=r"(r[2]), "=r"(r[3]) : "r"(a));
}
__device__ __forceinline__ void mma_f16(float* d, const uint32_t* a, const uint32_t* b) {
    asm volatile(
        "mma.sync.aligned.m16n8k16.row.col.f32.f16.f16.f32 "
        "{%0,%1,%2,%3}, {%4,%5,%6,%7}, {%8,%9}, {%0,%1,%2,%3};"
        : "+f"(d[0]), "+f"(d[1]), "+f"(d[2]), "+f"(d[3])
        : "r"(a[0]), "r"(a[1]), "r"(a[2]), "r"(a[3]), "r"(b[0]), "r"(b[1]));
}
__device__ __forceinline__ void mma_f16h(uint32_t* d, const uint32_t* a, const uint32_t* b) {
    asm volatile(
        "mma.sync.aligned.m16n8k16.row.col.f16.f16.f16.f16 "
        "{%0,%1}, {%2,%3,%4,%5}, {%6,%7}, {%0,%1};"
        : "+r"(d[0]), "+r"(d[1])
        : "r"(a[0]), "r"(a[1]), "r"(a[2]), "r"(a[3]), "r"(b[0]), "r"(b[1]));
}

// ---------------- weight/bias staging ----------------
__global__ void cvt_w_kernel(const float* __restrict__ w0, const float* __restrict__ w1,
                             const float* __restrict__ w2, const float* __restrict__ w3,
                             const float* __restrict__ b0, const float* __restrict__ b1,
                             const float* __restrict__ b2,
                             __half* __restrict__ dst, float* __restrict__ bdst) {
    const int n = CH * CH;
    const float* srcs[4] = {w0, w1, w2, w3};
    for (int idx = blockIdx.x * blockDim.x + threadIdx.x; idx < 4 * n;
         idx += gridDim.x * blockDim.x)
        dst[idx] = __float2half(srcs[idx / n][idx % n]);
    if (blockIdx.x == 0) {
        const float* bs[3] = {b0, b1, b2};
        for (int idx = threadIdx.x; idx < 3 * CH; idx += blockDim.x)
            bdst[idx] = bs[idx / CH][idx % CH];
    }
}

// ---------------- GroupNorm pass 1: partial stats -> slots (no atomics) ----
__global__ void gn_stats_kernel(const float* __restrict__ x,
                                float (*__restrict__ stats)[8][2]) {
    const int bg   = blockIdx.x >> 3;
    const int part = blockIdx.x & 7;
    const float4* xp = reinterpret_cast<const float4*>(x) + (size_t)bg * 16384 + part * 2048;
    const int tid = threadIdx.x;

    float s = 0.f, ss = 0.f;
    #pragma unroll
    for (int i = 0; i < 8; i++) {
        float4 v = xp[tid + i * 256];
        s  += v.x + v.y + v.z + v.w;
        ss += v.x * v.x + v.y * v.y + v.z * v.z + v.w * v.w;
    }
    __shared__ float sh1[256], sh2[256];
    sh1[tid] = s; sh2[tid] = ss;
    __syncthreads();
    for (int o = 128; o > 0; o >>= 1) {
        if (tid < o) { sh1[tid] += sh1[tid + o]; sh2[tid] += sh2[tid + o]; }
        __syncthreads();
    }
    if (tid == 0) {
        stats[bg][part][0] = sh1[0];
        stats[bg][part][1] = sh2[0];
    }
}

// ---------------- GroupNorm pass 2: normalize + zero L (fp32 in, fp16 out) -
__global__ void gn_apply_kernel(const float* __restrict__ x,
                                const float* __restrict__ gamma,
                                const float* __restrict__ beta,
                                const float (*__restrict__ stats)[8][2],
                                __half* __restrict__ h,
                                float* __restrict__ L) {
    const size_t f = (size_t)blockIdx.x * blockDim.x + threadIdx.x;  // float4 index
    // fold row-sum zeroing into this pass (L consumed only by the later QK kernel)
    if (f < (size_t)BATCH * HWN) L[f] = 0.f;

    const int per_b = CH * HWN / 4;
    const int b = (int)(f / per_b);
    const int r = (int)(f % per_b);
    const int c = r / (HWN / 4);
    const int bg = b * NGROUPS + c / CPG;

    float sum = 0.f, sumsq = 0.f;
    #pragma unroll
    for (int p = 0; p < 8; p++) { sum += stats[bg][p][0]; sumsq += stats[bg][p][1]; }
    const float mean = sum * (1.f / 65536.f);
    const float var  = sumsq * (1.f / 65536.f) - mean * mean;
    const float inv  = rsqrtf(var + 1e-6f);
    const float sc = gamma[c] * inv;
    const float of = beta[c] - mean * sc;

    float4 v = reinterpret_cast<const float4*>(x)[f];
    __half2 h01 = __floats2half2_rn(v.x * sc + of, v.y * sc + of);
    __half2 h23 = __floats2half2_rn(v.z * sc + of, v.w * sc + of);
    uint2 pk;
    pk.x = *reinterpret_cast<uint32_t*>(&h01);
    pk.y = *reinterpret_cast<uint32_t*>(&h23);
    reinterpret_cast<uint2*>(h)[f] = pk;
}

// ---------------- FP16 tensor-core GEMM, 3-stage cp.async, TK=64 -----------
// C[m,n] = op(A)*op(B); ATRANS: A stored [K,M]; BTRANS: B stored [N,K]
// EPI: 2 +bias+res (float out, f32 acc), 6 merged QKV +bias (half out, f32 acc),
//      4 exp+rowsum (half out, f16 acc), 5 col-normalize (half out, f16 acc)
template<bool ATRANS, bool BTRANS, int EPI>
__global__ __launch_bounds__(256, 2)
void gemm_f16(const __half* __restrict__ Ag, const __half* __restrict__ Bg,
              void* __restrict__ Cg,
              const float* __restrict__ bias, const float* __restrict__ res,
              float* __restrict__ Lsum,
              int K, int lda, int ldb, int ldc,
              size_t strA, size_t strB, size_t strC, float scale)
{
    extern __shared__ __half smem[];
    constexpr int SA = ATRANS ? (TM + 8) : (TK + 8);
    constexpr int SB = BTRANS ? (TK + 8) : (TN + 8);
    constexpr int SZA = ATRANS ? TK * SA : TM * SA;
    constexpr int SZB = BTRANS ? TN * SB : TK * SB;
    constexpr int STG = SZA + SZB;
    constexpr bool HAS_BIAS = (EPI == 2 || EPI == 6);
    constexpr bool F16ACC = (EPI == 4 || EPI == 5);
    constexpr int ACH = ATRANS ? TM / 8 : TK / 8;
    constexpr int ANR = ATRANS ? TK : TM;
    constexpr int BCH = BTRANS ? TK / 8 : TN / 8;
    constexpr int BNR = BTRANS ? TN : TK;

    const int zz = blockIdx.z;
    const int proj = (EPI == 6) ? (zz >> 2) : 0;
    const int bz   = (EPI == 6) ? (zz & 3)  : zz;
    const int m0 = blockIdx.y * TM;
    const int n0 = blockIdx.x * TN;
    const __half* A = Ag + ((EPI == 6) ? (size_t)proj * CH * CH : (size_t)bz * strA);
    const __half* B = Bg + (size_t)bz * strB;
    const size_t coff = (EPI == 6) ? ((size_t)proj * BATCH + bz) * strC
                                   : (size_t)bz * strC;
    const float* R = (EPI == 2) ? (res + coff) : nullptr;
    const float* Bi = HAS_BIAS ? (bias + ((EPI == 6) ? proj * CH : 0)) : nullptr;
    float* L = (EPI == 4 || EPI == 5) ? (Lsum + (size_t)bz * HWN) : nullptr;

    const int tid  = threadIdx.x;
    const int wid  = tid >> 5;
    const int lane = tid & 31;
    const int gid  = lane >> 2;
    const int tig  = lane & 3;
    const int wm   = (wid >> 2) * 64;
    const int wn   = (wid & 3) * 32;
    const int lq   = lane >> 3;
    const int lr   = lane & 7;

    auto copy_tile = [&](int kt, int st) {
        __half* as = smem + st * STG;
        __half* bs = as + SZA;
        const int k0 = kt * TK;
        #pragma unroll
        for (int i = 0; i < ANR * ACH / 256; i++) {
            int idx = tid + i * 256;
            int r = idx / ACH, c = idx % ACH;
            if (ATRANS)
                cp16(smem_u32(as + r * SA + c * 8), A + (size_t)(k0 + r) * lda + m0 + c * 8);
            else
                cp16(smem_u32(as + r * SA + c * 8), A + (size_t)(m0 + r) * lda + k0 + c * 8);
        }
        #pragma unroll
        for (int i = 0; i < BNR * BCH / 256; i++) {
            int idx = tid + i * 256;
            int r = idx / BCH, c = idx % BCH;
            if (BTRANS)
                cp16(smem_u32(bs + r * SB + c * 8), B + (size_t)(n0 + r) * ldb + k0 + c * 8);
            else
                cp16(smem_u32(bs + r * SB + c * 8), B + (size_t)(k0 + r) * ldb + n0 + c * 8);
        }
    };

    float    accf[4][4][4] = {};
    uint32_t acch[4][4][2] = {};
    const int KT = K / TK;

    copy_tile(0, 0); cp_commit();
    copy_tile(1, 1); cp_commit();

    for (int kt = 0; kt < KT; kt++) {
        cp_wait<1>();
        __syncthreads();
        if (kt + 2 < KT) copy_tile(kt + 2, (kt + 2) % STAGES);
        cp_commit();

        const __half* as = smem + (kt % STAGES) * STG;
        const __half* bs = as + SZA;

        #pragma unroll
        for (int ks = 0; ks < TK / 16; ks++) {
            const int kk = ks * 16;
            uint32_t a[4][4], b[2][4];
            #pragma unroll
            for (int i = 0; i < 4; i++) {
                const int mb = wm + i * 16;
                if (ATRANS)
                    ldmx4t(a[i], smem_u32(as + (size_t)(kk + (lq >> 1) * 8 + lr) * SA
                                             + mb + (lq & 1) * 8));
                else
                    ldmx4(a[i], smem_u32(as + (size_t)(mb + lr + (lq & 1) * 8) * SA
                                            + kk + (lq >> 1) * 8));
            }
            #pragma unroll
            for (int jj = 0; jj < 2; jj++) {
                const int nb = wn + jj * 16;
                if (BTRANS)
                    ldmx4(b[jj], smem_u32(bs + (size_t)(nb + (lq >> 1) * 8 + lr) * SB
                                             + kk + (lq & 1) * 8));
                else
                    ldmx4t(b[jj], smem_u32(bs + (size_t)(kk + (lq & 1) * 8 + lr) * SB
                                              + nb + (lq >> 1) * 8));
            }
            #pragma unroll
            for (int i = 0; i < 4; i++)
                #pragma unroll
                for (int j = 0; j < 4; j++) {
                    if (F16ACC) mma_f16h(acch[i][j], a[i], &b[j >> 1][(j & 1) * 2]);
                    else        mma_f16 (accf[i][j], a[i], &b[j >> 1][(j & 1) * 2]);
                }
        }
    }

    __syncthreads();

    // ---- epilogue ----
    #pragma unroll
    for (int i = 0; i < 4; i++) {
        const int r0 = m0 + wm + i * 16 + gid;
        float b0v = 0.f, b1v = 0.f;
        if (HAS_BIAS) { b0v = Bi[r0]; b1v = Bi[r0 + 8]; }
        float rsum0 = 0.f, rsum1 = 0.f;
        #pragma unroll
        for (int j = 0; j < 4; j++) {
            const int c0 = n0 + wn + j * 8 + tig * 2;
            size_t i0 = (size_t)r0 * ldc + c0;
            size_t i1 = (size_t)(r0 + 8) * ldc + c0;
            float2 v0, v1;
            if (F16ACC) {
                __half2 p0 = *reinterpret_cast<__half2*>(&acch[i][j][0]);
                __half2 p1 = *reinterpret_cast<__half2*>(&acch[i][j][1]);
                v0 = __half22float2(p0);
                v1 = __half22float2(p1);
            } else {
                v0 = make_float2(accf[i][j][0], accf[i][j][1]);
                v1 = make_float2(accf[i][j][2], accf[i][j][3]);
            }
            if (HAS_BIAS) { v0.x += b0v; v0.y += b0v; v1.x += b1v; v1.y += b1v; }
            if (EPI == 2) {
                float2 r0v = *reinterpret_cast<const float2*>(&R[i0]);
                float2 r1v = *reinterpret_cast<const float2*>(&R[i1]);
                v0.x += r0v.x; v0.y += r0v.y; v1.x += r1v.x; v1.y += r1v.y;
            }
            if (EPI == 4) {
                v0.x = __expf(v0.x * scale); v0.y = __expf(v0.y * scale);
                v1.x = __expf(v1.x * scale); v1.y = __expf(v1.y * scale);
                rsum0 += v0.x + v0.y;
                rsum1 += v1.x + v1.y;
            }
            if (EPI == 5) {
                float l0 = L[c0], l1 = L[c0 + 1];
                v0.x /= l0; v0.y /= l1;
                v1.x /= l0; v1.y /= l1;
            }
            if (EPI == 2) {
                float* C = (float*)Cg + coff;
                *reinterpret_cast<float2*>(&C[i0]) = v0;
                *reinterpret_cast<float2*>(&C[i1]) = v1;
            } else {
                __half* C = (__half*)Cg + coff;
                *reinterpret_cast<__half2*>(&C[i0]) = __floats2half2_rn(v0.x, v0.y);
                *reinterpret_cast<__half2*>(&C[i1]) = __floats2half2_rn(v1.x, v1.y);
            }
        }
        if (EPI == 4) {
            rsum0 += __shfl_xor_sync(0xffffffffu, rsum0, 1);
            rsum0 += __shfl_xor_sync(0xffffffffu, rsum0, 2);
            rsum1 += __shfl_xor_sync(0xffffffffu, rsum1, 1);
            rsum1 += __shfl_xor_sync(0xffffffffu, rsum1, 2);
            if (tig == 0) {
                atomicAdd(&L[r0], rsum0);
                atomicAdd(&L[r0 + 8], rsum1);
            }
        }
    }
}

// ---------------- launch ----------------
extern "C" void kernel_launch(void* const* d_in, const int* in_sizes, int n_in,
                              void* d_out, int out_size) {
    const float* x        = (const float*)d_in[0];
    const float* gn_gamma = (const float*)d_in[1];
    const float* gn_beta  = (const float*)d_in[2];
    const float* wq       = (const float*)d_in[3];
    const float* bq       = (const float*)d_in[4];
    const float* wk       = (const float*)d_in[5];
    const float* bk       = (const float*)d_in[6];
    const float* wv       = (const float*)d_in[7];
    const float* bv       = (const float*)d_in[8];
    const float* wo       = (const float*)d_in[9];
    const float* bo       = (const float*)d_in[10];
    float* out = (float*)d_out;

    __half *ph, *pqkv, *po, *ps, *pw;
    float *pl, *pb;
    float (*pst)[8][2];
    cudaGetSymbolAddress((void**)&ph, g_h);
    cudaGetSymbolAddress((void**)&pqkv, g_qkv);
    cudaGetSymbolAddress((void**)&po, g_o);
    cudaGetSymbolAddress((void**)&ps, g_s);
    cudaGetSymbolAddress((void**)&pl, g_l);
    cudaGetSymbolAddress((void**)&pw, g_w);
    cudaGetSymbolAddress((void**)&pb, g_bias);
    cudaGetSymbolAddress((void**)&pst, g_stats);

    const size_t sCH = (size_t)CH * HWN;
    const size_t sSS = (size_t)HWN * HWN;
    const float scale = 0.04419417382415922f; // 512^-0.5
    const int WS = CH * CH;
    __half* pq = pqkv;
    __half* pk = pqkv + (size_t)BATCH * sCH;
    __half* pv = pqkv + 2 * (size_t)BATCH * sCH;

    const int smem_ff = STAGES * (TM * (TK + 8) + TK * (TN + 8)) * 2;
    const int smem_tf = STAGES * (TK * (TM + 8) + TK * (TN + 8)) * 2;
    const int smem_ft = STAGES * (TM * (TK + 8) + TN * (TK + 8)) * 2;

    cudaFuncSetAttribute(gemm_f16<false, false, 6>, cudaFuncAttributeMaxDynamicSharedMemorySize, smem_ff);
    cudaFuncSetAttribute(gemm_f16<false, false, 2>, cudaFuncAttributeMaxDynamicSharedMemorySize, smem_ff);
    cudaFuncSetAttribute(gemm_f16<true,  false, 4>, cudaFuncAttributeMaxDynamicSharedMemorySize, smem_tf);
    cudaFuncSetAttribute(gemm_f16<false, true,  5>, cudaFuncAttributeMaxDynamicSharedMemorySize, smem_ft);

    // 0) weights/biases -> staged
    cvt_w_kernel<<<256, 256>>>(wq, wk, wv, wo, bq, bk, bv, pw, pb);

    // 1) GroupNorm: partial stats (slot writes) then apply (+ L zeroing) -> fp16 h
    gn_stats_kernel<<<BATCH * NGROUPS * 8, 256>>>(x, pst);
    gn_apply_kernel<<<(int)(BATCH * sCH / 4 / 256), 256>>>(x, gn_gamma, gn_beta, pst, ph, pl);

    // 2) merged q,k,v projections: z = proj*4 + batch
    dim3 pg3(HWN / TN, CH / TM, 3 * BATCH);
    gemm_f16<false, false, 6><<<pg3, 256, smem_ff>>>(pw, ph, pqkv, pb, nullptr, nullptr,
        CH, CH, HWN, HWN, 0, sCH, sCH, 1.f);

    // 3) P~[n,m] = exp(scale * Q^T K) (fp16), row sums -> g_l  [f16 acc]
    dim3 sg(HWN / TN, HWN / TM, BATCH);
    gemm_f16<true, false, 4><<<sg, 256, smem_tf>>>(pq, pk, ps, nullptr, nullptr, pl,
        CH, HWN, HWN, HWN, sCH, sCH, sSS, scale);

    // 4) O[c,n] = (sum_m V[c,m] P~[n,m]) / l[n] (fp16)  [f16 acc]
    dim3 ag(HWN / TN, CH / TM, BATCH);
    gemm_f16<false, true, 5><<<ag, 256, smem_ft>>>(pv, ps, po, nullptr, nullptr, pl,
        HWN, HWN, HWN, HWN, sCH, sSS, sCH, 1.f);

    // 5) out projection + bias + residual (fp32 out)
    dim3 pg(HWN / TN, CH / TM, BATCH);
    gemm_f16<false, false, 2><<<pg, 256, smem_ff>>>(pw + 3 * WS, po, out, bo, x, nullptr,
        CH, CH, HWN, HWN, 0, sCH, sCH, 1.f);
}